// round 1
// baseline (speedup 1.0000x reference)
#include <cuda_runtime.h>
#include <cuda_bf16.h>
#include <math.h>

// Problem constants
#define Bz   2
#define Cc   512
#define Tt   16
#define HWp  1024      // 32*32
#define Ss   64
#define Dd   1024
#define Gg   32
#define CPG  16        // channels per group
#define EPS  1e-5f
#define SCALE 0.04419417382415922f  // 512^-0.5
#define FULLMASK 0xffffffffu

// ---------------- scratch (device globals; no allocations) ----------------
__device__ float g_mu  [Bz * Gg * Tt];          // 1024
__device__ float g_rstd[Bz * Gg * Tt];          // 1024
__device__ float g_kv  [Bz * Ss * 2 * Cc];      // 131072
__device__ float g_kp  [Bz * Ss * Cc];          // 65536  (k' = Wq^T k)
__device__ float g_vp  [Bz * Ss * Cc];          // 65536  (v' = Wo  v)
__device__ float g_ksb [Bz * Ss];               // 128    (bq . k)

// ---------------- kernel 1: groupnorm stats per (b,g,t) -------------------
__global__ void gn_stats_kernel(const float* __restrict__ x) {
    int idx = blockIdx.x;                 // = b*512 + g*16 + t
    int b = idx >> 9;
    int g = (idx >> 4) & 31;
    int t = idx & 15;
    int tid = threadIdx.x;                // 256 threads

    float s = 0.f, sq = 0.f;
    for (int ci = 0; ci < CPG; ci++) {
        const float4* row = (const float4*)(x + (size_t)(((b*Cc + g*CPG + ci)*Tt + t)) * HWp);
        float4 v = row[tid];              // 256 float4 = 1024 elems
        s  += v.x + v.y + v.z + v.w;
        sq += v.x*v.x + v.y*v.y + v.z*v.z + v.w*v.w;
    }
    __shared__ float s1[256], s2[256];
    s1[tid] = s; s2[tid] = sq;
    __syncthreads();
    for (int st = 128; st > 0; st >>= 1) {
        if (tid < st) { s1[tid] += s1[tid + st]; s2[tid] += s2[tid + st]; }
        __syncthreads();
    }
    if (tid == 0) {
        const float invN = 1.f / (CPG * HWp);
        float mu  = s1[0] * invN;
        float var = s2[0] * invN - mu * mu;
        g_mu[idx]   = mu;
        g_rstd[idx] = rsqrtf(var + EPS);
    }
}

// ---------------- kernel 2: generic small tiled SGEMM ---------------------
// C[M,N] = A[M,K] * op(B) + bias ;  op(B)=B (row-major KxN) if !BT else B^T (B row-major NxK)
template<bool BT>
__global__ void sgemm_tile(const float* __restrict__ A, int lda,
                           const float* __restrict__ B, int ldb,
                           float* __restrict__ C, int ldc,
                           const float* __restrict__ bias, int K) {
    __shared__ float As[16][68];
    __shared__ float Bs[16][68];
    int m0 = blockIdx.y * 64, n0 = blockIdx.x * 64;
    int tid = threadIdx.x;                 // 256
    int tx = tid & 15, ty = tid >> 4;

    float acc[4][4];
    #pragma unroll
    for (int i = 0; i < 4; i++)
        #pragma unroll
        for (int j = 0; j < 4; j++) acc[i][j] = 0.f;

    for (int k0 = 0; k0 < K; k0 += 16) {
        // A tile: As[k][m]
        {
            int mm = tid >> 2, kb = (tid & 3) << 2;
            float4 av = *(const float4*)&A[(size_t)(m0 + mm) * lda + k0 + kb];
            As[kb+0][mm] = av.x; As[kb+1][mm] = av.y;
            As[kb+2][mm] = av.z; As[kb+3][mm] = av.w;
        }
        // B tile: Bs[k][n]
        if (!BT) {
            int kk = tid >> 4, nb = (tid & 15) << 2;
            float4 bv = *(const float4*)&B[(size_t)(k0 + kk) * ldb + n0 + nb];
            *(float4*)&Bs[kk][nb] = bv;
        } else {
            int nn = tid >> 2, kb = (tid & 3) << 2;
            float4 bv = *(const float4*)&B[(size_t)(n0 + nn) * ldb + k0 + kb];
            Bs[kb+0][nn] = bv.x; Bs[kb+1][nn] = bv.y;
            Bs[kb+2][nn] = bv.z; Bs[kb+3][nn] = bv.w;
        }
        __syncthreads();
        #pragma unroll
        for (int kk = 0; kk < 16; kk++) {
            float4 a4 = *(const float4*)&As[kk][ty << 2];
            float4 b4 = *(const float4*)&Bs[kk][tx << 2];
            float a[4] = {a4.x, a4.y, a4.z, a4.w};
            float bb[4] = {b4.x, b4.y, b4.z, b4.w};
            #pragma unroll
            for (int i = 0; i < 4; i++)
                #pragma unroll
                for (int j = 0; j < 4; j++)
                    acc[i][j] += a[i] * bb[j];
        }
        __syncthreads();
    }
    float bj[4];
    #pragma unroll
    for (int j = 0; j < 4; j++) bj[j] = bias ? bias[n0 + (tx << 2) + j] : 0.f;
    #pragma unroll
    for (int i = 0; i < 4; i++) {
        float4 r;
        r.x = acc[i][0] + bj[0]; r.y = acc[i][1] + bj[1];
        r.z = acc[i][2] + bj[2]; r.w = acc[i][3] + bj[3];
        *(float4*)&C[(size_t)(m0 + (ty << 2) + i) * ldc + n0 + (tx << 2)] = r;
    }
}

// ---------------- kernel 3: bq . k  ---------------------------------------
__global__ void ksb_kernel(const float* __restrict__ bq) {
    int m = blockIdx.x;                 // 0..127 (= b*64 + s)
    int tid = threadIdx.x;              // 256
    float s = 0.f;
    for (int o = tid; o < Cc; o += 256) s += bq[o] * g_kv[(size_t)m * (2*Cc) + o];
    __shared__ float red[256];
    red[tid] = s;
    __syncthreads();
    for (int st = 128; st > 0; st >>= 1) {
        if (tid < st) red[tid] += red[tid + st];
        __syncthreads();
    }
    if (tid == 0) g_ksb[m] = red[0];
}

// ---------------- kernel 4: fused normalize + attention + out -------------
// block per (b, t, 64-hw tile); 512 threads = 16 warps, 4 queries/warp
__global__ void __launch_bounds__(512) attn_kernel(
    const float* __restrict__ x, const float* __restrict__ gamma,
    const float* __restrict__ beta, const float* __restrict__ bo,
    float* __restrict__ out) {
    extern __shared__ float sh[];       // [64][516]  h then reused for o
    const int STR = 516;
    int bi = blockIdx.x;
    int tile = bi & 15, t = (bi >> 4) & 15, b = bi >> 8;
    int hw0 = tile * 64;
    int tid = threadIdx.x;

    // ---- stage normalized h[hw][c] in smem (coalesced x reads) ----
    {
        const float* mub = g_mu   + b * 512 + t;
        const float* rsb = g_rstd + b * 512 + t;
        for (int it = 0; it < 16; it++) {
            int lin = it * 512 + tid;        // 0..8191
            int c  = lin >> 4;
            int hw = (lin & 15) << 2;
            float4 xv = *(const float4*)(x + (size_t)(((b*Cc + c)*Tt + t)) * HWp + hw0 + hw);
            int g = c >> 4;
            float m_ = mub[g * 16];
            float r_ = rsb[g * 16];
            float scl = r_ * gamma[c];
            float bia = beta[c] - m_ * scl;
            sh[(hw+0)*STR + c] = xv.x * scl + bia;
            sh[(hw+1)*STR + c] = xv.y * scl + bia;
            sh[(hw+2)*STR + c] = xv.z * scl + bia;
            sh[(hw+3)*STR + c] = xv.w * scl + bia;
        }
    }
    __syncthreads();

    const int L = (t + 1) * 4;           // block-causal visible keys
    int warp = tid >> 5, lane = tid & 31;
    const float* kpb  = g_kp  + (size_t)b * Ss * Cc;
    const float* vpb  = g_vp  + (size_t)b * Ss * Cc;
    const float* ksbb = g_ksb + b * Ss;

    for (int qi = 0; qi < 4; qi++) {
        int q = warp * 4 + qi;
        float4 h4[4];
        #pragma unroll
        for (int i = 0; i < 4; i++)
            h4[i] = *(const float4*)&sh[q * STR + ((i*32 + lane) << 2)];

        // ---- scores ----
        float sc0 = -INFINITY, sc1 = -INFINITY;
        for (int s = 0; s < L; s++) {
            const float4* kr = (const float4*)(kpb + (size_t)s * Cc);
            float a = 0.f;
            #pragma unroll
            for (int i = 0; i < 4; i++) {
                float4 k4 = kr[i*32 + lane];
                a += h4[i].x*k4.x + h4[i].y*k4.y + h4[i].z*k4.z + h4[i].w*k4.w;
            }
            #pragma unroll
            for (int off = 16; off > 0; off >>= 1) a += __shfl_xor_sync(FULLMASK, a, off);
            a = (a + ksbb[s]) * SCALE;
            if (s < 32) { if (lane == s)      sc0 = a; }
            else        { if (lane == s - 32) sc1 = a; }
        }
        // ---- softmax over <=64 values held 2-per-lane ----
        float mx = fmaxf(sc0, sc1);
        #pragma unroll
        for (int off = 16; off > 0; off >>= 1) mx = fmaxf(mx, __shfl_xor_sync(FULLMASK, mx, off));
        float e0 = __expf(sc0 - mx), e1 = __expf(sc1 - mx);   // exp(-inf)=0 for masked
        float ds = e0 + e1;
        #pragma unroll
        for (int off = 16; off > 0; off >>= 1) ds += __shfl_xor_sync(FULLMASK, ds, off);
        float inv = 1.f / ds;
        float w0 = e0 * inv, w1 = e1 * inv;

        // ---- combine with v' ----
        float4 acc[4];
        #pragma unroll
        for (int i = 0; i < 4; i++) acc[i] = make_float4(0.f, 0.f, 0.f, 0.f);
        int Lc = L < 32 ? L : 32;
        for (int s = 0; s < Lc; s++) {
            float ws = __shfl_sync(FULLMASK, w0, s);
            const float4* vr = (const float4*)(vpb + (size_t)s * Cc);
            #pragma unroll
            for (int i = 0; i < 4; i++) {
                float4 vv = vr[i*32 + lane];
                acc[i].x += ws*vv.x; acc[i].y += ws*vv.y;
                acc[i].z += ws*vv.z; acc[i].w += ws*vv.w;
            }
        }
        for (int s = 32; s < L; s++) {
            float ws = __shfl_sync(FULLMASK, w1, s - 32);
            const float4* vr = (const float4*)(vpb + (size_t)s * Cc);
            #pragma unroll
            for (int i = 0; i < 4; i++) {
                float4 vv = vr[i*32 + lane];
                acc[i].x += ws*vv.x; acc[i].y += ws*vv.y;
                acc[i].z += ws*vv.z; acc[i].w += ws*vv.w;
            }
        }
        // stash o into same smem row (rows are warp-private: no hazard)
        #pragma unroll
        for (int i = 0; i < 4; i++)
            *(float4*)&sh[q * STR + ((i*32 + lane) << 2)] = acc[i];
    }
    __syncthreads();

    // ---- write out: out = x + o + bo, coalesced over hw ----
    for (int it = 0; it < 64; it++) {
        int lin = it * 512 + tid;            // 0..32767
        int c = lin >> 6, hw = lin & 63;
        size_t gidx = (size_t)(((b*Cc + c)*Tt + t)) * HWp + hw0 + hw;
        out[gidx] = x[gidx] + sh[hw * STR + c] + bo[c];
    }
}

// ---------------- launch ---------------------------------------------------
extern "C" void kernel_launch(void* const* d_in, const int* in_sizes, int n_in,
                              void* d_out, int out_size) {
    const float* x       = (const float*)d_in[0];
    const float* context = (const float*)d_in[1];
    const float* gamma   = (const float*)d_in[2];
    const float* beta    = (const float*)d_in[3];
    const float* wq      = (const float*)d_in[4];
    const float* bq      = (const float*)d_in[5];
    const float* wkv     = (const float*)d_in[6];
    const float* bkv     = (const float*)d_in[7];
    const float* wo      = (const float*)d_in[8];
    const float* bo      = (const float*)d_in[9];
    float* out = (float*)d_out;

    float *p_kv, *p_kp, *p_vp;
    cudaGetSymbolAddress((void**)&p_kv, g_kv);
    cudaGetSymbolAddress((void**)&p_kp, g_kp);
    cudaGetSymbolAddress((void**)&p_vp, g_vp);

    const int SMEM_BYTES = 64 * 516 * 4;   // 132096
    cudaFuncSetAttribute(attn_kernel, cudaFuncAttributeMaxDynamicSharedMemorySize, SMEM_BYTES);

    // 1. groupnorm stats
    gn_stats_kernel<<<Bz * Gg * Tt, 256>>>(x);

    // 2. kv = context @ wkv^T + bkv   [128, 1024]
    sgemm_tile<true><<<dim3(16, 2), 256>>>(context, Dd, wkv, Dd, p_kv, 2*Cc, bkv, Dd);

    // 3. k' = k @ wq  [128, 512]  (k = kv[:, :512])
    sgemm_tile<false><<<dim3(8, 2), 256>>>(p_kv, 2*Cc, wq, Cc, p_kp, Cc, nullptr, Cc);

    // 4. v' = v @ wo^T [128, 512] (v = kv[:, 512:])
    sgemm_tile<true><<<dim3(8, 2), 256>>>(p_kv + Cc, 2*Cc, wo, Cc, p_vp, Cc, nullptr, Cc);

    // 5. score bias bq . k
    ksb_kernel<<<Bz * Ss, 256>>>(bq);

    // 6. fused normalize + attention + output projection + residual
    attn_kernel<<<Bz * Tt * (HWp / 64), 512, SMEM_BYTES>>>(x, gamma, beta, bo, out);
}

// round 2
// speedup vs baseline: 1.8637x; 1.8637x over previous
#include <cuda_runtime.h>
#include <cuda_bf16.h>
#include <math.h>

#define Bz   2
#define Cc   512
#define Tt   16
#define HWp  1024
#define Ss   64
#define Dd   1024
#define EPS  1e-5f
#define SCALE 0.04419417382415922f  // 512^-0.5
#define FULLMASK 0xffffffffu
#define STR  516                     // h row stride in smem
#define KSTR 68                      // kT chunk row stride
#define VSTR 132                     // v chunk row stride
#define SSTR 68                      // score row stride

// ---------------- scratch ----------------
__device__ float g_mu  [Bz * 32 * Tt];
__device__ float g_rstd[Bz * 32 * Tt];
__device__ float g_kv  [128 * 1024];      // [b*64+s][2C]
__device__ float g_kpT [512 * 128];       // kT: [c][b*64+s]
__device__ float g_vp  [128 * 512];       // [b*64+s][c]
__device__ float g_ksb [128];             // bq . k

// ---------------- groupnorm stats ----------------
__global__ void gn_stats_kernel(const float* __restrict__ x) {
    int idx = blockIdx.x;                 // b*512 + g*16 + t
    int b = idx >> 9, g = (idx >> 4) & 31, t = idx & 15;
    int tid = threadIdx.x;
    float s = 0.f, sq = 0.f;
    for (int ci = 0; ci < 16; ci++) {
        const float4* row = (const float4*)(x + (size_t)(((b*Cc + g*16 + ci)*Tt + t)) * HWp);
        float4 v = row[tid];
        s  += v.x + v.y + v.z + v.w;
        sq += v.x*v.x + v.y*v.y + v.z*v.z + v.w*v.w;
    }
    __shared__ float s1[256], s2[256];
    s1[tid] = s; s2[tid] = sq;
    __syncthreads();
    for (int st = 128; st > 0; st >>= 1) {
        if (tid < st) { s1[tid] += s1[tid + st]; s2[tid] += s2[tid + st]; }
        __syncthreads();
    }
    if (tid == 0) {
        const float invN = 1.f / 16384.f;
        float mu  = s1[0] * invN;
        float var = s2[0] * invN - mu * mu;
        g_mu[idx] = mu;
        g_rstd[idx] = rsqrtf(var + EPS);
    }
}

// ---------------- seed: g_kv = bkv (broadcast), g_kpT = 0, g_vp = 0 ----------------
__global__ void seed_kernel(const float* __restrict__ bkv) {
    int i = blockIdx.x * 256 + threadIdx.x;   // 0 .. 262143
    if (i < 131072)       g_kv[i]          = bkv[i & 1023];
    else if (i < 196608)  g_kpT[i-131072]  = 0.f;
    else                  g_vp[i-196608]   = 0.f;
}

// ---------------- split-K tiled SGEMM with atomic epilogue ----------------
// C (+)= A[M,K] * op(B); op(B)=B if !BT else B^T; CT: store C transposed
template<bool BT, bool CT>
__global__ void sgemm2(const float* __restrict__ A, int lda,
                       const float* __restrict__ B, int ldb,
                       float* __restrict__ C, int ldc, int Kchunk) {
    __shared__ float As[16][68];
    __shared__ float Bs[16][68];
    int m0 = blockIdx.y * 64, n0 = blockIdx.x * 64;
    int k0base = blockIdx.z * Kchunk;
    int tid = threadIdx.x;
    int tx = tid & 15, ty = tid >> 4;

    float acc[4][4];
    #pragma unroll
    for (int i = 0; i < 4; i++)
        #pragma unroll
        for (int j = 0; j < 4; j++) acc[i][j] = 0.f;

    for (int k0 = k0base; k0 < k0base + Kchunk; k0 += 16) {
        {
            int mm = tid >> 2, kb = (tid & 3) << 2;
            float4 av = *(const float4*)&A[(size_t)(m0 + mm) * lda + k0 + kb];
            As[kb+0][mm] = av.x; As[kb+1][mm] = av.y;
            As[kb+2][mm] = av.z; As[kb+3][mm] = av.w;
        }
        if (!BT) {
            int kk = tid >> 4, nb = (tid & 15) << 2;
            float4 bv = *(const float4*)&B[(size_t)(k0 + kk) * ldb + n0 + nb];
            *(float4*)&Bs[kk][nb] = bv;
        } else {
            int nn = tid >> 2, kb = (tid & 3) << 2;
            float4 bv = *(const float4*)&B[(size_t)(n0 + nn) * ldb + k0 + kb];
            Bs[kb+0][nn] = bv.x; Bs[kb+1][nn] = bv.y;
            Bs[kb+2][nn] = bv.z; Bs[kb+3][nn] = bv.w;
        }
        __syncthreads();
        #pragma unroll
        for (int kk = 0; kk < 16; kk++) {
            float4 a4 = *(const float4*)&As[kk][ty << 2];
            float4 b4 = *(const float4*)&Bs[kk][tx << 2];
            float a[4] = {a4.x, a4.y, a4.z, a4.w};
            float bb[4] = {b4.x, b4.y, b4.z, b4.w};
            #pragma unroll
            for (int i = 0; i < 4; i++)
                #pragma unroll
                for (int j = 0; j < 4; j++)
                    acc[i][j] += a[i] * bb[j];
        }
        __syncthreads();
    }
    #pragma unroll
    for (int i = 0; i < 4; i++)
        #pragma unroll
        for (int j = 0; j < 4; j++) {
            int m = m0 + (ty << 2) + i, n = n0 + (tx << 2) + j;
            if (CT) atomicAdd(&C[(size_t)n * ldc + m], acc[i][j]);
            else    atomicAdd(&C[(size_t)m * ldc + n], acc[i][j]);
        }
}

// ---------------- bq . k ----------------
__global__ void ksb_kernel(const float* __restrict__ bq) {
    int m = blockIdx.x;
    int tid = threadIdx.x;
    float s = 0.f;
    for (int o = tid; o < Cc; o += 256) s += bq[o] * g_kv[(size_t)m * 1024 + o];
    __shared__ float red[256];
    red[tid] = s;
    __syncthreads();
    for (int st = 128; st > 0; st >>= 1) {
        if (tid < st) red[tid] += red[tid + st];
        __syncthreads();
    }
    if (tid == 0) g_ksb[m] = red[0];
}

// ---------------- fused normalize + attention + residual ----------------
// block per (b, t, 64-hw tile); 512 threads
__global__ void __launch_bounds__(512) attn_kernel(
    const float* __restrict__ x, const float* __restrict__ gamma,
    const float* __restrict__ beta, const float* __restrict__ bo,
    float* __restrict__ out) {
    extern __shared__ float sh[];
    float* sh_h = sh;                      // 64 x STR (h, later o)
    float* sh_k = sh + 64 * STR;           // kT chunk 128xKSTR  /  v chunk 64xVSTR
    float* sh_s = sh_k + 128 * KSTR;       // scores 64 x SSTR

    int bi = blockIdx.x;
    int tile = bi & 15, t = (bi >> 4) & 15, b = bi >> 8;
    int hw0 = tile * 64;
    int tid = threadIdx.x;
    const int L = (t + 1) * 4;

    // ---- stage normalized h[hw][c] ----
    {
        const float* mub = g_mu   + b * 512 + t;
        const float* rsb = g_rstd + b * 512 + t;
        for (int it = 0; it < 16; it++) {
            int lin = it * 512 + tid;
            int c  = lin >> 4;
            int hw = (lin & 15) << 2;
            float4 xv = *(const float4*)(x + (size_t)(((b*Cc + c)*Tt + t)) * HWp + hw0 + hw);
            int g = c >> 4;
            float scl = rsb[g * 16] * gamma[c];
            float bia = beta[c] - mub[g * 16] * scl;
            sh_h[(hw+0)*STR + c] = xv.x * scl + bia;
            sh_h[(hw+1)*STR + c] = xv.y * scl + bia;
            sh_h[(hw+2)*STR + c] = xv.z * scl + bia;
            sh_h[(hw+3)*STR + c] = xv.w * scl + bia;
        }
    }
    __syncthreads();

    int warp = tid >> 5, lane = tid & 31;

    // ================= scores: S = h @ kT =================
    // warp tile 16q x 16s; lane: ly=lane>>2 (rows ly, ly+8), lx=lane&3 (4 s cols)
    {
        int qw = warp >> 2, sw = warp & 3;
        int q0 = qw * 16, s0 = sw * 16;
        int ly = lane >> 2, lx = lane & 3;
        float acc0[4] = {0.f,0.f,0.f,0.f}, acc1[4] = {0.f,0.f,0.f,0.f};
        bool active = (s0 < L);

        for (int c0 = 0; c0 < 512; c0 += 128) {
            // cooperative load kT chunk: rows c0..c0+127, 64 s each
            #pragma unroll
            for (int i = 0; i < 4; i++) {
                int idx = i * 512 + tid;          // 0..2047 (float4 units)
                int cc = idx >> 4, sf = (idx & 15) << 2;
                float4 v = *(const float4*)&g_kpT[(size_t)(c0 + cc) * 128 + b * 64 + sf];
                *(float4*)&sh_k[cc * KSTR + sf] = v;
            }
            __syncthreads();
            if (active) {
                #pragma unroll 4
                for (int c = 0; c < 128; c += 4) {
                    float4 a0 = *(const float4*)&sh_h[(q0 + ly    ) * STR + c0 + c];
                    float4 a1 = *(const float4*)&sh_h[(q0 + ly + 8) * STR + c0 + c];
                    float av0[4] = {a0.x, a0.y, a0.z, a0.w};
                    float av1[4] = {a1.x, a1.y, a1.z, a1.w};
                    #pragma unroll
                    for (int j = 0; j < 4; j++) {
                        float4 bv = *(const float4*)&sh_k[(c + j) * KSTR + s0 + (lx << 2)];
                        acc0[0] += av0[j]*bv.x; acc0[1] += av0[j]*bv.y;
                        acc0[2] += av0[j]*bv.z; acc0[3] += av0[j]*bv.w;
                        acc1[0] += av1[j]*bv.x; acc1[1] += av1[j]*bv.y;
                        acc1[2] += av1[j]*bv.z; acc1[3] += av1[j]*bv.w;
                    }
                }
            }
            __syncthreads();
        }
        if (active) {
            const float* ksbb = g_ksb + b * 64;
            #pragma unroll
            for (int j = 0; j < 4; j++) {
                int s = s0 + (lx << 2) + j;
                if (s < L) {
                    float kb = ksbb[s];
                    sh_s[(q0 + ly    ) * SSTR + s] = (acc0[j] + kb) * SCALE;
                    sh_s[(q0 + ly + 8) * SSTR + s] = (acc1[j] + kb) * SCALE;
                }
            }
        }
    }
    __syncthreads();

    // ================= softmax: warp handles 4 rows =================
    {
        for (int r = 0; r < 4; r++) {
            int q = warp * 4 + r;
            float v0 = (lane      < L) ? sh_s[q * SSTR + lane     ] : -INFINITY;
            float v1 = (lane + 32 < L) ? sh_s[q * SSTR + lane + 32] : -INFINITY;
            float mx = fmaxf(v0, v1);
            #pragma unroll
            for (int off = 16; off > 0; off >>= 1) mx = fmaxf(mx, __shfl_xor_sync(FULLMASK, mx, off));
            float e0 = __expf(v0 - mx), e1 = __expf(v1 - mx);
            float ds = e0 + e1;
            #pragma unroll
            for (int off = 16; off > 0; off >>= 1) ds += __shfl_xor_sync(FULLMASK, ds, off);
            float inv = 1.f / ds;
            if (lane      < L) sh_s[q * SSTR + lane     ] = e0 * inv;
            if (lane + 32 < L) sh_s[q * SSTR + lane + 32] = e1 * inv;
        }
    }

    // ================= combine: O = W @ v' =================
    // warp tile 16q x 32c; lane: ly2=lane>>3 (q rows +0,4,8,12), lx2=lane&7 (float4 c)
    {
        int qw = warp >> 2, cw = warp & 3;
        int q0 = qw * 16;
        int ly2 = lane >> 3, lx2 = lane & 7;
        int coff = cw * 32 + (lx2 << 2);

        for (int c0 = 0; c0 < 512; c0 += 128) {
            __syncthreads();   // protect sh_k (prev chunk / score phase) before overwrite
            #pragma unroll
            for (int i = 0; i < 4; i++) {
                int idx = i * 512 + tid;          // 0..2047 (float4 units)
                int s = idx >> 5, col = (idx & 31) << 2;
                float4 v = *(const float4*)&g_vp[(size_t)(b * 64 + s) * 512 + c0 + col];
                *(float4*)&sh_k[s * VSTR + col] = v;
            }
            __syncthreads();

            float4 acc[4];
            #pragma unroll
            for (int k = 0; k < 4; k++) acc[k] = make_float4(0.f,0.f,0.f,0.f);

            for (int s = 0; s < L; s += 2) {
                float2 w0 = *(const float2*)&sh_s[(q0 + ly2     ) * SSTR + s];
                float2 w1 = *(const float2*)&sh_s[(q0 + ly2 +  4) * SSTR + s];
                float2 w2 = *(const float2*)&sh_s[(q0 + ly2 +  8) * SSTR + s];
                float2 w3 = *(const float2*)&sh_s[(q0 + ly2 + 12) * SSTR + s];
                float4 va = *(const float4*)&sh_k[ s      * VSTR + coff];
                float4 vb = *(const float4*)&sh_k[(s + 1) * VSTR + coff];
                acc[0].x += w0.x*va.x + w0.y*vb.x; acc[0].y += w0.x*va.y + w0.y*vb.y;
                acc[0].z += w0.x*va.z + w0.y*vb.z; acc[0].w += w0.x*va.w + w0.y*vb.w;
                acc[1].x += w1.x*va.x + w1.y*vb.x; acc[1].y += w1.x*va.y + w1.y*vb.y;
                acc[1].z += w1.x*va.z + w1.y*vb.z; acc[1].w += w1.x*va.w + w1.y*vb.w;
                acc[2].x += w2.x*va.x + w2.y*vb.x; acc[2].y += w2.x*va.y + w2.y*vb.y;
                acc[2].z += w2.x*va.z + w2.y*vb.z; acc[2].w += w2.x*va.w + w2.y*vb.w;
                acc[3].x += w3.x*va.x + w3.y*vb.x; acc[3].y += w3.x*va.y + w3.y*vb.y;
                acc[3].z += w3.x*va.z + w3.y*vb.z; acc[3].w += w3.x*va.w + w3.y*vb.w;
            }
            #pragma unroll
            for (int k = 0; k < 4; k++)
                *(float4*)&sh_h[(q0 + ly2 + 4*k) * STR + c0 + coff] = acc[k];
        }
    }
    __syncthreads();

    // ---- out = x + o + bo ----
    for (int it = 0; it < 64; it++) {
        int lin = it * 512 + tid;
        int c = lin >> 6, hw = lin & 63;
        size_t gidx = (size_t)(((b*Cc + c)*Tt + t)) * HWp + hw0 + hw;
        out[gidx] = x[gidx] + sh_h[hw * STR + c] + bo[c];
    }
}

// ---------------- launch ----------------
extern "C" void kernel_launch(void* const* d_in, const int* in_sizes, int n_in,
                              void* d_out, int out_size) {
    const float* x       = (const float*)d_in[0];
    const float* context = (const float*)d_in[1];
    const float* gamma   = (const float*)d_in[2];
    const float* beta    = (const float*)d_in[3];
    const float* wq      = (const float*)d_in[4];
    const float* bq      = (const float*)d_in[5];
    const float* wkv     = (const float*)d_in[6];
    const float* bkv     = (const float*)d_in[7];
    const float* wo      = (const float*)d_in[8];
    const float* bo      = (const float*)d_in[9];
    float* out = (float*)d_out;

    float *p_kv, *p_kpT, *p_vp;
    cudaGetSymbolAddress((void**)&p_kv,  g_kv);
    cudaGetSymbolAddress((void**)&p_kpT, g_kpT);
    cudaGetSymbolAddress((void**)&p_vp,  g_vp);

    const int SMEM_BYTES = (64*STR + 128*KSTR + 64*SSTR) * 4;  // 184320
    cudaFuncSetAttribute(attn_kernel, cudaFuncAttributeMaxDynamicSharedMemorySize, SMEM_BYTES);

    // independent preproc
    seed_kernel<<<1024, 256>>>(bkv);
    gn_stats_kernel<<<1024, 256>>>(x);

    // kv = context @ wkv^T (+bkv seeded)   M=128 N=1024 K=1024, Ksplit=4
    sgemm2<true, false><<<dim3(16, 2, 4), 256>>>(context, Dd, wkv, Dd, p_kv, 1024, 256);
    // bq . k
    ksb_kernel<<<128, 256>>>(bq);
    // kT = (k @ wq)^T   M=128 N=512 K=512, Ksplit=2, stored transposed [c][128]
    sgemm2<false, true><<<dim3(8, 2, 2), 256>>>(p_kv, 1024, wq, Cc, p_kpT, 128, 256);
    // v' = v @ wo^T     M=128 N=512 K=512, Ksplit=2
    sgemm2<true, false><<<dim3(8, 2, 2), 256>>>(p_kv + Cc, 1024, wo, Cc, p_vp, Cc, 256);

    // fused attention
    attn_kernel<<<Bz * Tt * 16, 512, SMEM_BYTES>>>(x, gamma, beta, bo, out);
}

// round 3
// speedup vs baseline: 2.4745x; 1.3277x over previous
#include <cuda_runtime.h>
#include <cuda_bf16.h>
#include <math.h>

#define Bz   2
#define Cc   512
#define Tt   16
#define HWp  1024
#define EPS  1e-5f
#define SCALE 0.04419417382415922f  // 512^-0.5
#define FULLMASK 0xffffffffu
#define STR  516
#define KSTR 68
#define VSTR 132
#define SSTR 68

typedef unsigned long long ull;

// ---------------- f32x2 helpers ----------------
__device__ __forceinline__ ull pack2(float v) {
    ull r; asm("mov.b64 %0, {%1, %1};" : "=l"(r) : "f"(v)); return r;
}
__device__ __forceinline__ void fma2(ull& a, ull x, ull y) {
    asm("fma.rn.f32x2 %0, %1, %2, %0;" : "+l"(a) : "l"(x), "l"(y));
}
__device__ __forceinline__ float2 unpack2(ull v) {
    float2 f; asm("mov.b64 {%0, %1}, %2;" : "=f"(f.x), "=f"(f.y) : "l"(v)); return f;
}

// ---------------- scratch ----------------
__device__ float g_mu  [Bz * 32 * Tt];
__device__ float g_rstd[Bz * 32 * Tt];
__device__ float g_kv  [128 * 1024];      // [b*64+s][2C]
__device__ float g_kpT [512 * 128];       // [c][b*64+s]
__device__ float g_vp  [128 * 512];       // [b*64+s][c]
__device__ float g_ksb [128];

// ---------------- groupnorm stats ----------------
__global__ void gn_stats_kernel(const float* __restrict__ x) {
    int idx = blockIdx.x;                 // b*512 + g*16 + t
    int b = idx >> 9, g = (idx >> 4) & 31, t = idx & 15;
    int tid = threadIdx.x;
    float s = 0.f, sq = 0.f;
    for (int ci = 0; ci < 16; ci++) {
        const float4* row = (const float4*)(x + (size_t)(((b*Cc + g*16 + ci)*Tt + t)) * HWp);
        float4 v = row[tid];
        s  += v.x + v.y + v.z + v.w;
        sq += v.x*v.x + v.y*v.y + v.z*v.z + v.w*v.w;
    }
    __shared__ float s1[256], s2[256];
    s1[tid] = s; s2[tid] = sq;
    __syncthreads();
    for (int st = 128; st > 0; st >>= 1) {
        if (tid < st) { s1[tid] += s1[tid + st]; s2[tid] += s2[tid + st]; }
        __syncthreads();
    }
    if (tid == 0) {
        const float invN = 1.f / 16384.f;
        float mu  = s1[0] * invN;
        float var = s2[0] * invN - mu * mu;
        g_mu[idx] = mu;
        g_rstd[idx] = rsqrtf(var + EPS);
    }
}

// ---------------- seed ----------------
__global__ void seed_kernel(const float* __restrict__ bkv) {
    int i = blockIdx.x * 256 + threadIdx.x;
    if (i < 131072)       g_kv[i]         = bkv[i & 1023];
    else if (i < 196608)  g_kpT[i-131072] = 0.f;
    else                  g_vp[i-196608]  = 0.f;
}

// ---------------- kv = context @ wkv^T (split-K, atomic) ----------------
__global__ void kv_gemm(const float* __restrict__ A, const float* __restrict__ B) {
    __shared__ float As[16][68];
    __shared__ float Bs[16][68];
    int m0 = blockIdx.y * 64, n0 = blockIdx.x * 64;
    int k0base = blockIdx.z * 256;
    int tid = threadIdx.x;
    int tx = tid & 15, ty = tid >> 4;

    float acc[4][4];
    #pragma unroll
    for (int i = 0; i < 4; i++)
        #pragma unroll
        for (int j = 0; j < 4; j++) acc[i][j] = 0.f;

    for (int k0 = k0base; k0 < k0base + 256; k0 += 16) {
        {
            int mm = tid >> 2, kb = (tid & 3) << 2;
            float4 av = *(const float4*)&A[(size_t)(m0 + mm) * 1024 + k0 + kb];
            As[kb+0][mm] = av.x; As[kb+1][mm] = av.y;
            As[kb+2][mm] = av.z; As[kb+3][mm] = av.w;
        }
        {   // B^T: B row-major [N,K]
            int nn = tid >> 2, kb = (tid & 3) << 2;
            float4 bv = *(const float4*)&B[(size_t)(n0 + nn) * 1024 + k0 + kb];
            Bs[kb+0][nn] = bv.x; Bs[kb+1][nn] = bv.y;
            Bs[kb+2][nn] = bv.z; Bs[kb+3][nn] = bv.w;
        }
        __syncthreads();
        #pragma unroll
        for (int kk = 0; kk < 16; kk++) {
            float4 a4 = *(const float4*)&As[kk][ty << 2];
            float4 b4 = *(const float4*)&Bs[kk][tx << 2];
            float a[4] = {a4.x, a4.y, a4.z, a4.w};
            float bb[4] = {b4.x, b4.y, b4.z, b4.w};
            #pragma unroll
            for (int i = 0; i < 4; i++)
                #pragma unroll
                for (int j = 0; j < 4; j++)
                    acc[i][j] += a[i] * bb[j];
        }
        __syncthreads();
    }
    #pragma unroll
    for (int i = 0; i < 4; i++)
        #pragma unroll
        for (int j = 0; j < 4; j++)
            atomicAdd(&g_kv[(size_t)(m0 + (ty<<2) + i) * 1024 + n0 + (tx<<2) + j], acc[i][j]);
}

// ---------------- proj2: kT gemm (0-31), vp gemm (32-63), ksb (64-67) ----------------
__global__ void proj2_kernel(const float* __restrict__ wq, const float* __restrict__ wo,
                             const float* __restrict__ bq) {
    int bid = blockIdx.x;
    int tid = threadIdx.x;

    if (bid >= 64) {          // ksb: bq . k  (32 rows per block, warp handles 4 rows)
        int warp = tid >> 5, lane = tid & 31;
        int base = (bid - 64) * 32 + warp * 4;
        for (int r = 0; r < 4; r++) {
            int row = base + r;
            const float4* kr = (const float4*)&g_kv[(size_t)row * 1024];
            float s = 0.f;
            #pragma unroll
            for (int i = 0; i < 4; i++) {
                float4 kvv = kr[i*32 + lane];
                float4 bqv = *(const float4*)&bq[(i*32 + lane) << 2];
                s += kvv.x*bqv.x + kvv.y*bqv.y + kvv.z*bqv.z + kvv.w*bqv.w;
            }
            #pragma unroll
            for (int off = 16; off > 0; off >>= 1) s += __shfl_xor_sync(FULLMASK, s, off);
            if (lane == 0) g_ksb[row] = s;
        }
        return;
    }

    __shared__ float As[16][68];
    __shared__ float Bs[16][68];
    bool isK = bid < 32;
    int local = bid & 31;
    int n0 = (local & 7) * 64;
    int m0 = ((local >> 3) & 1) * 64;
    int k0base = (local >> 4) * 256;
    const float* A = isK ? g_kv : (g_kv + 512);
    const float* B = isK ? wq : wo;
    int tx = tid & 15, ty = tid >> 4;

    float acc[4][4];
    #pragma unroll
    for (int i = 0; i < 4; i++)
        #pragma unroll
        for (int j = 0; j < 4; j++) acc[i][j] = 0.f;

    for (int k0 = k0base; k0 < k0base + 256; k0 += 16) {
        {
            int mm = tid >> 2, kb = (tid & 3) << 2;
            float4 av = *(const float4*)&A[(size_t)(m0 + mm) * 1024 + k0 + kb];
            As[kb+0][mm] = av.x; As[kb+1][mm] = av.y;
            As[kb+2][mm] = av.z; As[kb+3][mm] = av.w;
        }
        if (isK) {            // B = wq, not transposed: Bs[k][n] = B[k*512 + n]
            int kk = tid >> 4, nb = (tid & 15) << 2;
            float4 bv = *(const float4*)&B[(size_t)(k0 + kk) * 512 + n0 + nb];
            *(float4*)&Bs[kk][nb] = bv;
        } else {              // B = wo^T
            int nn = tid >> 2, kb = (tid & 3) << 2;
            float4 bv = *(const float4*)&B[(size_t)(n0 + nn) * 512 + k0 + kb];
            Bs[kb+0][nn] = bv.x; Bs[kb+1][nn] = bv.y;
            Bs[kb+2][nn] = bv.z; Bs[kb+3][nn] = bv.w;
        }
        __syncthreads();
        #pragma unroll
        for (int kk = 0; kk < 16; kk++) {
            float4 a4 = *(const float4*)&As[kk][ty << 2];
            float4 b4 = *(const float4*)&Bs[kk][tx << 2];
            float a[4] = {a4.x, a4.y, a4.z, a4.w};
            float bb[4] = {b4.x, b4.y, b4.z, b4.w};
            #pragma unroll
            for (int i = 0; i < 4; i++)
                #pragma unroll
                for (int j = 0; j < 4; j++)
                    acc[i][j] += a[i] * bb[j];
        }
        __syncthreads();
    }
    #pragma unroll
    for (int i = 0; i < 4; i++)
        #pragma unroll
        for (int j = 0; j < 4; j++) {
            int m = m0 + (ty << 2) + i, n = n0 + (tx << 2) + j;
            if (isK) atomicAdd(&g_kpT[(size_t)n * 128 + m], acc[i][j]);   // transposed
            else     atomicAdd(&g_vp [(size_t)m * 512 + n], acc[i][j]);
        }
}

// ---------------- fused normalize + attention + residual ----------------
// block per (b, t, 32-hw tile); 256 threads; ~110KB smem -> 2 CTAs/SM
__global__ void __launch_bounds__(256) attn_kernel(
    const float* __restrict__ x, const float* __restrict__ gamma,
    const float* __restrict__ beta, const float* __restrict__ bo,
    float* __restrict__ out) {
    extern __shared__ float sh[];
    float* sh_h = sh;                      // 32 x STR
    float* sh_k = sh + 32 * STR;           // kT 128xKSTR  /  v 64xVSTR
    float* sh_s = sh_k + 128 * KSTR;       // 32 x SSTR

    int bi = blockIdx.x;
    int tile = bi & 31, t = 15 - ((bi >> 5) & 15), b = bi >> 9;
    int hw0 = tile * 32;
    int tid = threadIdx.x;
    const int L = (t + 1) * 4;

    // ---- stage normalized h[hw][c] ----
    {
        const float* mub = g_mu   + b * 512 + t;
        const float* rsb = g_rstd + b * 512 + t;
        #pragma unroll
        for (int it = 0; it < 16; it++) {
            int lin = it * 256 + tid;        // 0..4095
            int c  = lin >> 3;
            int hw = (lin & 7) << 2;
            float4 xv = *(const float4*)(x + (size_t)(((b*Cc + c)*Tt + t)) * HWp + hw0 + hw);
            int g = c >> 4;
            float scl = rsb[g * 16] * gamma[c];
            float bia = beta[c] - mub[g * 16] * scl;
            sh_h[(hw+0)*STR + c] = xv.x * scl + bia;
            sh_h[(hw+1)*STR + c] = xv.y * scl + bia;
            sh_h[(hw+2)*STR + c] = xv.z * scl + bia;
            sh_h[(hw+3)*STR + c] = xv.w * scl + bia;
        }
    }
    __syncthreads();

    int warp = tid >> 5, lane = tid & 31;

    // ================= scores: S = h @ kT (f32x2) =================
    {
        int qw = warp >> 2, sw = warp & 3;
        int q0 = qw * 16, s0 = sw * 16;
        int ly = lane >> 2, lx = lane & 3;
        ull a00 = 0, a01 = 0, a10 = 0, a11 = 0;   // 2 rows x 2 pairs
        bool active = (s0 < L);

        for (int c0 = 0; c0 < 512; c0 += 128) {
            // load kT chunk (L-aware)
            #pragma unroll
            for (int i = 0; i < 8; i++) {
                int idx = i * 256 + tid;           // 0..2047 float4 units
                int cc = idx >> 4, sf = (idx & 15) << 2;
                if (sf < L) {
                    float4 v = *(const float4*)&g_kpT[(size_t)(c0 + cc) * 128 + b * 64 + sf];
                    *(float4*)&sh_k[cc * KSTR + sf] = v;
                }
            }
            __syncthreads();
            if (active) {
                #pragma unroll 2
                for (int c = 0; c < 128; c += 4) {
                    float4 h0 = *(const float4*)&sh_h[(q0 + ly    ) * STR + c0 + c];
                    float4 h1 = *(const float4*)&sh_h[(q0 + ly + 8) * STR + c0 + c];
                    const float* kb = &sh_k[c * KSTR + s0 + (lx << 2)];
                    ulonglong2 b0 = *(const ulonglong2*)(kb);
                    ulonglong2 b1 = *(const ulonglong2*)(kb + KSTR);
                    ulonglong2 b2 = *(const ulonglong2*)(kb + 2*KSTR);
                    ulonglong2 b3 = *(const ulonglong2*)(kb + 3*KSTR);
                    ull p;
                    p = pack2(h0.x); fma2(a00, p, b0.x); fma2(a01, p, b0.y);
                    p = pack2(h1.x); fma2(a10, p, b0.x); fma2(a11, p, b0.y);
                    p = pack2(h0.y); fma2(a00, p, b1.x); fma2(a01, p, b1.y);
                    p = pack2(h1.y); fma2(a10, p, b1.x); fma2(a11, p, b1.y);
                    p = pack2(h0.z); fma2(a00, p, b2.x); fma2(a01, p, b2.y);
                    p = pack2(h1.z); fma2(a10, p, b2.x); fma2(a11, p, b2.y);
                    p = pack2(h0.w); fma2(a00, p, b3.x); fma2(a01, p, b3.y);
                    p = pack2(h1.w); fma2(a10, p, b3.x); fma2(a11, p, b3.y);
                }
            }
            __syncthreads();
        }
        if (active) {
            const float* ksbb = g_ksb + b * 64;
            float2 r00 = unpack2(a00), r01 = unpack2(a01);
            float2 r10 = unpack2(a10), r11 = unpack2(a11);
            float sc0[4] = {r00.x, r00.y, r01.x, r01.y};
            float sc1[4] = {r10.x, r10.y, r11.x, r11.y};
            #pragma unroll
            for (int j = 0; j < 4; j++) {
                int s = s0 + (lx << 2) + j;
                if (s < L) {
                    float kb = ksbb[s];
                    sh_s[(q0 + ly    ) * SSTR + s] = (sc0[j] + kb) * SCALE;
                    sh_s[(q0 + ly + 8) * SSTR + s] = (sc1[j] + kb) * SCALE;
                }
            }
        }
    }
    __syncthreads();

    // ================= softmax (warp = 4 rows) =================
    for (int r = 0; r < 4; r++) {
        int q = warp * 4 + r;
        float v0 = (lane      < L) ? sh_s[q * SSTR + lane     ] : -INFINITY;
        float v1 = (lane + 32 < L) ? sh_s[q * SSTR + lane + 32] : -INFINITY;
        float mx = fmaxf(v0, v1);
        #pragma unroll
        for (int off = 16; off > 0; off >>= 1) mx = fmaxf(mx, __shfl_xor_sync(FULLMASK, mx, off));
        float e0 = __expf(v0 - mx), e1 = __expf(v1 - mx);
        float ds = e0 + e1;
        #pragma unroll
        for (int off = 16; off > 0; off >>= 1) ds += __shfl_xor_sync(FULLMASK, ds, off);
        float inv = 1.f / ds;
        if (lane      < L) sh_s[q * SSTR + lane     ] = e0 * inv;
        if (lane + 32 < L) sh_s[q * SSTR + lane + 32] = e1 * inv;
    }

    // ================= combine: O = W @ v' (f32x2) =================
    {
        int qw = warp >> 2, cw = warp & 3;
        int q0 = qw * 16;
        int ly2 = lane >> 3, lx2 = lane & 7;
        int coff = cw * 32 + (lx2 << 2);

        for (int c0 = 0; c0 < 512; c0 += 128) {
            __syncthreads();
            #pragma unroll
            for (int i = 0; i < 8; i++) {
                int idx = i * 256 + tid;            // 0..2047 float4 units
                int s = idx >> 5, col = (idx & 31) << 2;
                if (s < L) {
                    float4 v = *(const float4*)&g_vp[(size_t)(b * 64 + s) * 512 + c0 + col];
                    *(float4*)&sh_k[s * VSTR + col] = v;
                }
            }
            __syncthreads();

            ull acc[4][2];
            #pragma unroll
            for (int k = 0; k < 4; k++) { acc[k][0] = 0; acc[k][1] = 0; }

            for (int s = 0; s < L; s += 2) {
                ulonglong2 va = *(const ulonglong2*)&sh_k[ s      * VSTR + coff];
                ulonglong2 vb = *(const ulonglong2*)&sh_k[(s + 1) * VSTR + coff];
                #pragma unroll
                for (int k = 0; k < 4; k++) {
                    float2 w = *(const float2*)&sh_s[(q0 + ly2 + 4*k) * SSTR + s];
                    ull p;
                    p = pack2(w.x); fma2(acc[k][0], p, va.x); fma2(acc[k][1], p, va.y);
                    p = pack2(w.y); fma2(acc[k][0], p, vb.x); fma2(acc[k][1], p, vb.y);
                }
            }
            #pragma unroll
            for (int k = 0; k < 4; k++) {
                float2 f0 = unpack2(acc[k][0]), f1 = unpack2(acc[k][1]);
                float4 r; r.x = f0.x; r.y = f0.y; r.z = f1.x; r.w = f1.y;
                *(float4*)&sh_h[(q0 + ly2 + 4*k) * STR + c0 + coff] = r;
            }
        }
    }
    __syncthreads();

    // ---- out = x + o + bo ----
    #pragma unroll
    for (int it = 0; it < 64; it++) {
        int lin = it * 256 + tid;
        int c = lin >> 5, hw = lin & 31;
        size_t gidx = (size_t)(((b*Cc + c)*Tt + t)) * HWp + hw0 + hw;
        out[gidx] = x[gidx] + sh_h[hw * STR + c] + bo[c];
    }
}

// ---------------- launch ----------------
extern "C" void kernel_launch(void* const* d_in, const int* in_sizes, int n_in,
                              void* d_out, int out_size) {
    const float* x       = (const float*)d_in[0];
    const float* context = (const float*)d_in[1];
    const float* gamma   = (const float*)d_in[2];
    const float* beta    = (const float*)d_in[3];
    const float* wq      = (const float*)d_in[4];
    const float* bq      = (const float*)d_in[5];
    const float* wkv     = (const float*)d_in[6];
    const float* bkv     = (const float*)d_in[7];
    const float* wo      = (const float*)d_in[8];
    const float* bo      = (const float*)d_in[9];
    float* out = (float*)d_out;

    const int SMEM_BYTES = (32*STR + 128*KSTR + 32*SSTR) * 4;   // 109568
    static bool attr_set = false;
    cudaFuncSetAttribute(attn_kernel, cudaFuncAttributeMaxDynamicSharedMemorySize, SMEM_BYTES);
    (void)attr_set;

    seed_kernel<<<1024, 256>>>(bkv);
    gn_stats_kernel<<<1024, 256>>>(x);
    kv_gemm<<<dim3(16, 2, 4), 256>>>(context, wkv);
    proj2_kernel<<<68, 256>>>(wq, wo, bq);
    attn_kernel<<<Bz * Tt * 32, 256, SMEM_BYTES>>>(x, gamma, beta, bo, out);
}